// round 15
// baseline (speedup 1.0000x reference)
#include <cuda_runtime.h>
#include <cstdint>

// HashGrid2D: out[i] = table[bitmix_hash(floor(pos[i].x), floor(pos[i].y))]
// HASH_BITS=19, DIM=8, CELL_SIZE=1.0
//
// R10 winner structure (G=8, compiler-scheduled phases, pair-cooperative
// gather: 2 threads per 32B row -> adjacent lanes merge into one L1
// wavefront + one L2 sector per row; DEFAULT .ca gather -- R14 proved .cg
// breaks the pair-lane merge, +10us). Single delta this round:
// __launch_bounds__(256, 6) gives ptxas a 42-reg budget so it can hold a
// ~4-deep gather window in flight instead of the 2-deep it chose at 32 regs,
// trading a little occupancy (83% -> ~75%) for ~2x in-flight gathers.
//
// inputs: d_in[0] = positions [N,2] fp32, d_in[1] = table [2^19, 8] fp32
// output: [N, 8] fp32

#define HASH_BITS 19
#define HASH_MASK ((1u << HASH_BITS) - 1u)
#define G 8

__device__ __forceinline__ unsigned bitmix19(float px, float py)
{
    long long ix = (long long)floorf(px);   // CELL_SIZE = 1.0
    long long iy = (long long)floorf(py);
    long long h = ix;
    h ^= h >> 16;                           // arithmetic shift == jnp int64
    h *= 2246822507LL;
    h ^= h >> 13;
    h += iy * 3266489909LL;
    h ^= h >> 16;
    return (unsigned)h & HASH_MASK;         // mod 2^19, nonneg
}

template<bool GUARD>
__global__ __launch_bounds__(256, 6)        // 42-reg budget: deeper LDG pipeline
void hashgrid2d_g8_kernel(const float2* __restrict__ pos,
                          const float4* __restrict__ table,  // rows = 2x float4
                          float4* __restrict__ out,
                          int n2,                             // = 2*N slots
                          int T)                              // threads
{
    int t = blockIdx.x * blockDim.x + threadIdx.x;
    if (GUARD && t >= T) return;

    // ---- phase 1: batched streaming position loads (coalesced, pair-bcast)
    float2 p[G];
#pragma unroll
    for (int j = 0; j < G; j++) {
        int s = t + j * T;
        if (!GUARD || s < n2) p[j] = __ldcs(&pos[s >> 1]);
        else                  p[j] = make_float2(0.f, 0.f);
    }

    // ---- phase 2: hashes (int64 wraparound, matches jnp int64 semantics)
    unsigned idx[G];
#pragma unroll
    for (int j = 0; j < G; j++)
        idx[j] = bitmix19(p[j].x, p[j].y);

    // ---- phase 3: gathers -- DEFAULT caching (.ca): pair-lane requests to
    //               the same 128B line merge into one wavefront (R14: .cg
    //               defeats this merge and costs ~10us)
    float4 v[G];
#pragma unroll
    for (int j = 0; j < G; j++) {
        int s = t + j * T;
        if (!GUARD || s < n2)
            v[j] = table[((size_t)idx[j] << 1) + (s & 1)];
    }

    // ---- phase 4: coalesced streaming stores (evict-first: protect table L2)
#pragma unroll
    for (int j = 0; j < G; j++) {
        int s = t + j * T;
        if (!GUARD || s < n2)
            __stcs(&out[s], v[j]);
    }
}

extern "C" void kernel_launch(void* const* d_in, const int* in_sizes, int n_in,
                              void* d_out, int out_size)
{
    const float2* pos   = (const float2*)d_in[0];
    const float4* table = (const float4*)d_in[1];
    float4*       out   = (float4*)d_out;

    int n  = in_sizes[0] / 2;   // N positions
    int n2 = n * 2;             // pair slots
    int T  = (n2 + G - 1) / G;  // threads

    int threads = 256;
    int blocks  = (T + threads - 1) / threads;

    if (n2 % G == 0) {
        hashgrid2d_g8_kernel<false><<<blocks, threads>>>(pos, table, out, n2, T);
    } else {
        hashgrid2d_g8_kernel<true><<<blocks, threads>>>(pos, table, out, n2, T);
    }
}

// round 17
// speedup vs baseline: 1.1476x; 1.1476x over previous
#include <cuda_runtime.h>
#include <cstdint>

// HashGrid2D: out[i] = table[bitmix_hash(floor(pos[i].x), floor(pos[i].y))]
// HASH_BITS=19, DIM=8, CELL_SIZE=1.0
//
// Software-pipelined version of the R10 winner. Each thread handles 16 slots
// as ITERS=4 x G2=4 with next-iteration position loads issued BEFORE the
// current iteration's gathers, hiding the ~577cyc DRAM pos-load latency
// (the exposed head that was ~45% of warp lifetime in R10) behind L2-hit
// gathers. Pair-cooperative gather retained: adjacent lanes = adjacent slots
// -> one 128B line per 32B row -> 1 L1 wavefront + 1 L2 sector per row.
// Default .ca gathers (R14: .cg breaks the pair merge), .cs pos loads and
// stores (protect table's L2 residency). launch_bounds(256,7) caps regs at
// 36 to prevent the R13/R15 occupancy collapse.
//
// inputs: d_in[0] = positions [N,2] fp32, d_in[1] = table [2^19, 8] fp32
// output: [N, 8] fp32

#define HASH_BITS 19
#define HASH_MASK ((1u << HASH_BITS) - 1u)
#define G2     4
#define ITERS  4
#define BLK    256
#define SLOTS_PER_BLOCK (BLK * G2 * ITERS)   // 4096

__device__ __forceinline__ unsigned bitmix19(float px, float py)
{
    long long ix = (long long)floorf(px);   // CELL_SIZE = 1.0
    long long iy = (long long)floorf(py);
    long long h = ix;
    h ^= h >> 16;                           // arithmetic shift == jnp int64
    h *= 2246822507LL;
    h ^= h >> 13;
    h += iy * 3266489909LL;
    h ^= h >> 16;
    return (unsigned)h & HASH_MASK;         // mod 2^19, nonneg
}

// Fast path: n2 % SLOTS_PER_BLOCK == 0 (N = 2^23 -> 4096 blocks).
__global__ __launch_bounds__(BLK, 7)        // regs <= 36: protect occupancy
void hashgrid2d_pipe_kernel(const float2* __restrict__ pos,
                            const float4* __restrict__ table,  // rows = 2x float4
                            float4* __restrict__ out)
{
    const int tid  = threadIdx.x;
    const int base = blockIdx.x * SLOTS_PER_BLOCK + tid;   // slot of (it=0,j=0)
    const int half = base & 1;   // == tid&1: loop-invariant (strides are even)

    // ---- prologue: first iteration's position loads
    float2 p[G2];
#pragma unroll
    for (int j = 0; j < G2; j++)
        p[j] = __ldcs(&pos[(base + j * BLK) >> 1]);

#pragma unroll
    for (int it = 0; it < ITERS; it++) {
        const int ibase = base + it * (G2 * BLK);

        // hashes for current batch
        unsigned idx[G2];
#pragma unroll
        for (int j = 0; j < G2; j++)
            idx[j] = bitmix19(p[j].x, p[j].y);

        // ---- prefetch next iteration's positions BEFORE the gathers:
        //      their DRAM latency hides behind this iteration's L2 gathers
        if (it + 1 < ITERS) {
            const int nbase = base + (it + 1) * (G2 * BLK);
#pragma unroll
            for (int j = 0; j < G2; j++)
                p[j] = __ldcs(&pos[(nbase + j * BLK) >> 1]);
        }

        // gathers (default .ca: pair-lane merge into one wavefront per row)
        float4 v[G2];
#pragma unroll
        for (int j = 0; j < G2; j++)
            v[j] = table[((size_t)idx[j] << 1) + half];

        // coalesced streaming stores (evict-first: protect table in L2)
#pragma unroll
        for (int j = 0; j < G2; j++)
            __stcs(&out[ibase + j * BLK], v[j]);
    }
}

// Generic fallback (any N): one slot per thread, pair-cooperative.
__global__ __launch_bounds__(256)
void hashgrid2d_pair_kernel(const float2* __restrict__ pos,
                            const float4* __restrict__ table,
                            float4* __restrict__ out,
                            int n2)
{
    int t = blockIdx.x * blockDim.x + threadIdx.x;
    if (t >= n2) return;
    float2 p = pos[t >> 1];
    unsigned idx = bitmix19(p.x, p.y);
    out[t] = table[((size_t)idx << 1) + (t & 1)];
}

extern "C" void kernel_launch(void* const* d_in, const int* in_sizes, int n_in,
                              void* d_out, int out_size)
{
    const float2* pos   = (const float2*)d_in[0];
    const float4* table = (const float4*)d_in[1];
    float4*       out   = (float4*)d_out;

    int n  = in_sizes[0] / 2;   // N positions
    int n2 = n * 2;             // pair slots

    if (n2 % SLOTS_PER_BLOCK == 0) {
        int blocks = n2 / SLOTS_PER_BLOCK;   // 4096 for N = 2^23
        hashgrid2d_pipe_kernel<<<blocks, BLK>>>(pos, table, out);
    } else {
        int threads = 256;
        hashgrid2d_pair_kernel<<<(n2 + threads - 1) / threads, threads>>>(pos, table, out, n2);
    }
}